// round 12
// baseline (speedup 1.0000x reference)
#include <cuda_runtime.h>
#include <cuda_bf16.h>
#include <cuda_fp16.h>
#include <math.h>
#include <stdint.h>

#define L 4
#define NN 40000
#define D 128
#define KD 16
#define NE 320000
#define MROWS (L*NN)                 // 160000
#define SLICE ((size_t)NN*(size_t)D)
#define VST 132                      // LN staging row stride (floats)
#define AST 136                      // A smem row stride (bf16 elems)
#define BST 136                      // B smem/global row stride (bf16 elems, n-major)
#define WSZ (128*BST)                // one converted weight matrix (bf16 elems)
#define WST 33                       // Ws staging row stride (floats)

// byte offsets inside dynamic smem
#define AH_B 0
#define AL_B (64*AST*2)              // 17408
#define BH_B (2*64*AST*2)            // 34816
#define BL_B (BH_B + 128*BST*2)      // 69632
#define SMEM_GEMM (BL_B + 128*BST*2) // 104448

// prepw index ranges
#define PW_W    (4*128*128)          // 65536
#define PW_KQ   (PW_W + 32*128)      // +4096
#define PW_CNT  (PW_KQ + NN)         // +NN
#define PW_XH   (PW_CNT + (L*NN*D)/4)// + 5_120_000/4 float4 converts

__device__ __forceinline__ unsigned pkbf(__nv_bfloat16 a, __nv_bfloat16 b) {
    __nv_bfloat162 t = __halves2bfloat162(a, b);
    return *(unsigned*)&t;
}

__device__ __forceinline__ void mma16816(float c[4], const unsigned a[4], const unsigned b[2]) {
    asm volatile("mma.sync.aligned.m16n8k16.row.col.f32.bf16.bf16.f32 "
        "{%0,%1,%2,%3},{%4,%5,%6,%7},{%8,%9},{%0,%1,%2,%3};"
        : "+f"(c[0]), "+f"(c[1]), "+f"(c[2]), "+f"(c[3])
        : "r"(a[0]), "r"(a[1]), "r"(a[2]), "r"(a[3]), "r"(b[0]), "r"(b[1]));
}

// ---------------- device scratch ----------------
static __device__ float  g_S1[(size_t)L*NN*D];
static __device__ float  g_X [(size_t)L*NN*D];
static __device__ __half g_xh [(size_t)L*NN*D];   // fp16 copy of x (gather operand)
static __device__ __half g_s1h[(size_t)L*NN*D];   // fp16 copy of S1 (gather operand)
static __device__ int   g_rowptr[NN+1];
static __device__ int   g_cnt[NN];
static __device__ int   g_cur[NN];
static __device__ int   g_ecol[NE];
static __device__ float g_eval[NE];
static __device__ int   g_bsum[20];
// precomputed bf16 hi/lo weights, n-major [n*BST + k]; idx: 0=sage 1=agg 2=val 3=lin
static __device__ __align__(16) __nv_bfloat16 g_Wh[4*WSZ];
static __device__ __align__(16) __nv_bfloat16 g_Wl[4*WSZ];
// KQ = [Kw | Qw] bf16 hi/lo, n-major [n*128 + k]
static __device__ __align__(16) __nv_bfloat16 g_KQh[32*128];
static __device__ __align__(16) __nv_bfloat16 g_KQl[32*128];

// ---------------- prepw: weights+KQ bf16 hi/lo; zero CSR counters; x -> fp16 ----------------
__global__ __launch_bounds__(256) void k_prepw(const float* __restrict__ w0,
                                               const float* __restrict__ w1,
                                               const float* __restrict__ w2,
                                               const float* __restrict__ w3,
                                               const float* __restrict__ keyW,
                                               const float* __restrict__ qryW,
                                               const float* __restrict__ x) {
    int idx = blockIdx.x*blockDim.x + threadIdx.x;
    if (idx < PW_W) {
        int m = idx >> 14, r = idx & 16383, k = r >> 7, n = r & 127;
        const float* W = (m == 0) ? w0 : (m == 1) ? w1 : (m == 2) ? w2 : w3;
        float v = W[k*D + n];
        __nv_bfloat16 h = __float2bfloat16(v);
        __nv_bfloat16 l = __float2bfloat16(v - __bfloat162float(h));
        g_Wh[m*WSZ + n*BST + k] = h;
        g_Wl[m*WSZ + n*BST + k] = l;
    } else if (idx < PW_KQ) {
        int r = idx - PW_W, n = r >> 7, k = r & 127;
        float v = (n < KD) ? keyW[k*KD + n] : qryW[k*KD + (n - KD)];
        __nv_bfloat16 h = __float2bfloat16(v);
        __nv_bfloat16 l = __float2bfloat16(v - __bfloat162float(h));
        g_KQh[n*128 + k] = h;
        g_KQl[n*128 + k] = l;
    } else if (idx < PW_CNT) {
        int i = idx - PW_KQ;
        g_cnt[i] = 0; g_cur[i] = 0;
    } else if (idx < PW_XH) {
        size_t e = (size_t)(idx - PW_CNT);          // float4 index
        float4 v = ((const float4*)x)[e];
        __half2 h0 = __floats2half2_rn(v.x, v.y);
        __half2 h1 = __floats2half2_rn(v.z, v.w);
        *(uint2*)&g_xh[e*4] = make_uint2(*(unsigned*)&h0, *(unsigned*)&h1);
    }
}

// ---------------- CSR build ----------------
__global__ void k_hist(const int* __restrict__ rows) {
    int e = blockIdx.x*blockDim.x + threadIdx.x;
    if (e < NE) atomicAdd(&g_cnt[rows[e]], 1);
}

__global__ __launch_bounds__(1024) void k_scanA() {
    __shared__ int wsum[32];
    int t = threadIdx.x, b = blockIdx.x;
    int i0 = b*2048 + 2*t;
    int a = (i0     < NN) ? g_cnt[i0]   : 0;
    int c = (i0 + 1 < NN) ? g_cnt[i0+1] : 0;
    int pair = a + c;
    int lane = t & 31, wid = t >> 5;
    int v = pair;
    #pragma unroll
    for (int o = 1; o < 32; o <<= 1) {
        int tt = __shfl_up_sync(0xffffffffu, v, o);
        if (lane >= o) v += tt;
    }
    if (lane == 31) wsum[wid] = v;
    __syncthreads();
    if (wid == 0) {
        int s = wsum[lane];
        #pragma unroll
        for (int o = 1; o < 32; o <<= 1) {
            int tt = __shfl_up_sync(0xffffffffu, s, o);
            if (lane >= o) s += tt;
        }
        wsum[lane] = s;
    }
    __syncthreads();
    int excl = v - pair + ((wid > 0) ? wsum[wid-1] : 0);
    if (i0     < NN) g_rowptr[i0]   = excl;
    if (i0 + 1 < NN) g_rowptr[i0+1] = excl + a;
    if (t == 1023) g_bsum[b] = excl + pair;
}

__global__ void k_scanFix() {
    int i = blockIdx.x*blockDim.x + threadIdx.x;
    if (i <= NN) {
        int b = (i < NN) ? (i >> 11) : 20;
        int off = 0;
        for (int j = 0; j < b; ++j) off += g_bsum[j];
        if (i < NN) g_rowptr[i] += off;
        else        g_rowptr[NN] = off;
    }
}

__global__ void k_scatter(const int* __restrict__ rows, const int* __restrict__ cols,
                          const float* __restrict__ vals) {
    int e = blockIdx.x*blockDim.x + threadIdx.x;
    if (e < NE) {
        int r = rows[e];
        int p = atomicAdd(&g_cur[r], 1);
        int idx = g_rowptr[r] + p;
        g_ecol[idx] = cols[e];
        g_eval[idx] = vals[e];
    }
}

// ---------------- SPMM (fp16 gather, fp32 accumulate, 2-edge unroll) ----------------
// stage 0: gather g_xh -> write g_S1 (fp32) + g_s1h (fp16)
// stage 1: gather g_s1h -> write g_X = x + 0.5*S1 + 0.25*S2
__global__ __launch_bounds__(128) void k_spmm(const float* __restrict__ x, int stage) {
    const __half* __restrict__ in = (stage == 0) ? g_xh : g_s1h;
    int r = blockIdx.x;
    int d = threadIdx.x;
    int s  = g_rowptr[r];
    int e2 = g_rowptr[r+1];
    float a0 = 0.f, a1 = 0.f, a2 = 0.f, a3 = 0.f;
    int i = s;
    for (; i + 1 < e2; i += 2) {
        int   c0 = g_ecol[i],   c1 = g_ecol[i+1];
        float v0 = g_eval[i],   v1 = g_eval[i+1];
        const __half* p0 = in + (size_t)c0*D + d;
        const __half* p1 = in + (size_t)c1*D + d;
        float u0 = __half2float(p0[0]),        w0 = __half2float(p1[0]);
        float u1 = __half2float(p0[SLICE]),    w1 = __half2float(p1[SLICE]);
        float u2 = __half2float(p0[2*SLICE]),  w2 = __half2float(p1[2*SLICE]);
        float u3 = __half2float(p0[3*SLICE]),  w3 = __half2float(p1[3*SLICE]);
        a0 += v0*u0 + v1*w0;
        a1 += v0*u1 + v1*w1;
        a2 += v0*u2 + v1*w2;
        a3 += v0*u3 + v1*w3;
    }
    if (i < e2) {
        int   c = g_ecol[i];
        float v = g_eval[i];
        const __half* p = in + (size_t)c*D + d;
        a0 += v * __half2float(p[0]);
        a1 += v * __half2float(p[SLICE]);
        a2 += v * __half2float(p[2*SLICE]);
        a3 += v * __half2float(p[3*SLICE]);
    }
    size_t o = (size_t)r*D + d;
    if (stage == 0) {
        g_S1[o]           = a0;
        g_S1[o +   SLICE] = a1;
        g_S1[o + 2*SLICE] = a2;
        g_S1[o + 3*SLICE] = a3;
        g_s1h[o]           = __float2half(a0);
        g_s1h[o +   SLICE] = __float2half(a1);
        g_s1h[o + 2*SLICE] = __float2half(a2);
        g_s1h[o + 3*SLICE] = __float2half(a3);
    } else {
        // 0.5*S1 term from fp16 copy (error ~5e-4 of a 14% component — negligible)
        g_X[o]         = x[o]         + 0.5f*__half2float(in[o])         + 0.25f*a0;
        g_X[o+  SLICE] = x[o+  SLICE] + 0.5f*__half2float(in[o+  SLICE]) + 0.25f*a1;
        g_X[o+2*SLICE] = x[o+2*SLICE] + 0.5f*__half2float(in[o+2*SLICE]) + 0.25f*a2;
        g_X[o+3*SLICE] = x[o+3*SLICE] + 0.5f*__half2float(in[o+3*SLICE]) + 0.25f*a3;
    }
}

__device__ __forceinline__ float silu_f(float v) { return v / (1.f + expf(-v)); }

// inner MMA compute: k-step outer, split-passes inner — fragments loaded ONCE per kk
template<bool WQ>
__device__ __forceinline__ void mma_compute(char* dsm, int tid,
                                            float acc[2][4][4], float accW[2][4]) {
    int lane = tid & 31, w = tid >> 5;
    int wm = w >> 2, wn = w & 3;
    int g = lane >> 2, tc = (lane & 3)*2;
    int ar = wm*32 + g;
    const __nv_bfloat16* Ah = (const __nv_bfloat16*)(dsm + AH_B);
    const __nv_bfloat16* Al = (const __nv_bfloat16*)(dsm + AL_B);
    const __nv_bfloat16* Bh = (const __nv_bfloat16*)(dsm + BH_B);
    const __nv_bfloat16* Bl = (const __nv_bfloat16*)(dsm + BL_B);
    #pragma unroll
    for (int kk = 0; kk < 8; ++kk) {
        int k0 = kk*16;
        unsigned aH[2][4], aL[2][4], bH[4][2], bL[4][2];
        #pragma unroll
        for (int mf = 0; mf < 2; ++mf) {
            const __nv_bfloat16* bh = Ah + (ar + mf*16)*AST + k0 + tc;
            const __nv_bfloat16* bl = Al + (ar + mf*16)*AST + k0 + tc;
            aH[mf][0] = *(const unsigned*)(bh);
            aH[mf][1] = *(const unsigned*)(bh + 8*AST);
            aH[mf][2] = *(const unsigned*)(bh + 8);
            aH[mf][3] = *(const unsigned*)(bh + 8*AST + 8);
            aL[mf][0] = *(const unsigned*)(bl);
            aL[mf][1] = *(const unsigned*)(bl + 8*AST);
            aL[mf][2] = *(const unsigned*)(bl + 8);
            aL[mf][3] = *(const unsigned*)(bl + 8*AST + 8);
        }
        #pragma unroll
        for (int nf = 0; nf < 4; ++nf) {
            const __nv_bfloat16* bh = Bh + (wn*32 + nf*8 + g)*BST + k0 + tc;
            const __nv_bfloat16* bl = Bl + (wn*32 + nf*8 + g)*BST + k0 + tc;
            bH[nf][0] = *(const unsigned*)(bh);
            bH[nf][1] = *(const unsigned*)(bh + 8);
            bL[nf][0] = *(const unsigned*)(bl);
            bL[nf][1] = *(const unsigned*)(bl + 8);
        }
        #pragma unroll
        for (int mf = 0; mf < 2; ++mf)
            #pragma unroll
            for (int nf = 0; nf < 4; ++nf) {
                mma16816(acc[mf][nf], aH[mf], bH[nf]);   // Ah@Bh
                mma16816(acc[mf][nf], aL[mf], bH[nf]);   // Al@Bh
                mma16816(acc[mf][nf], aH[mf], bL[nf]);   // Ah@Bl
            }
        if (WQ) {
            const __nv_bfloat16* kh = g_KQh + (wn*8 + g)*128 + k0 + tc;
            const __nv_bfloat16* kl = g_KQl + (wn*8 + g)*128 + k0 + tc;
            unsigned kqH[2], kqL[2];
            kqH[0] = *(const unsigned*)(kh);
            kqH[1] = *(const unsigned*)(kh + 8);
            kqL[0] = *(const unsigned*)(kl);
            kqL[1] = *(const unsigned*)(kl + 8);
            mma16816(accW[0], aH[0], kqH);
            mma16816(accW[1], aH[1], kqH);
            mma16816(accW[0], aL[0], kqH);
            mma16816(accW[1], aL[1], kqH);
            mma16816(accW[0], aH[0], kqL);
            mma16816(accW[1], aH[1], kqL);
        }
    }
}

// full stage with A from global fp32
template<bool WQ>
__device__ __forceinline__ void mma_stage(const float* __restrict__ Agl,
                                          int widx, size_t m0, int tid, char* dsm,
                                          float acc[2][4][4], float accW[2][4]) {
    __syncthreads();
    {
        const float4* A4 = (const float4*)Agl;
        __nv_bfloat16* Ah = (__nv_bfloat16*)(dsm + AH_B);
        __nv_bfloat16* Al = (__nv_bfloat16*)(dsm + AL_B);
        #pragma unroll
        for (int i = tid; i < 64*32; i += 256) {
            int r = i >> 5, c4 = i & 31;
            float4 v = A4[(m0 + r)*32 + c4];
            __nv_bfloat16 h0 = __float2bfloat16(v.x), h1 = __float2bfloat16(v.y);
            __nv_bfloat16 h2 = __float2bfloat16(v.z), h3 = __float2bfloat16(v.w);
            __nv_bfloat16 l0 = __float2bfloat16(v.x - __bfloat162float(h0));
            __nv_bfloat16 l1 = __float2bfloat16(v.y - __bfloat162float(h1));
            __nv_bfloat16 l2 = __float2bfloat16(v.z - __bfloat162float(h2));
            __nv_bfloat16 l3 = __float2bfloat16(v.w - __bfloat162float(h3));
            *(uint2*)&Ah[r*AST + c4*4] = make_uint2(pkbf(h0, h1), pkbf(h2, h3));
            *(uint2*)&Al[r*AST + c4*4] = make_uint2(pkbf(l0, l1), pkbf(l2, l3));
        }
        const float4* srcH = (const float4*)(g_Wh + (size_t)widx*WSZ);
        const float4* srcL = (const float4*)(g_Wl + (size_t)widx*WSZ);
        float4* dH = (float4*)(dsm + BH_B);
        float4* dL = (float4*)(dsm + BL_B);
        #pragma unroll
        for (int i = tid; i < (128*BST)/8; i += 256) {
            dH[i] = srcH[i];
            dL[i] = srcL[i];
        }
    }
    __syncthreads();
    mma_compute<WQ>(dsm, tid, acc, accW);
}

// shared LN row-stats: Vs[64][VST] -> mu_s, rs_s
__device__ __forceinline__ void ln_stats(const float* Vs, float* mu_s, float* rs_s, int tid) {
    int w = tid >> 5, lane = tid & 31;
    for (int r = w; r < 64; r += 8) {
        float s = 0.f, q = 0.f;
        #pragma unroll
        for (int c = lane; c < 128; c += 32) { float v = Vs[r*VST + c]; s += v; q += v*v; }
        #pragma unroll
        for (int o = 16; o > 0; o >>= 1) {
            s += __shfl_down_sync(0xffffffffu, s, o);
            q += __shfl_down_sync(0xffffffffu, q, o);
        }
        if (lane == 0) {
            float mu = s * (1.f/128.f);
            float var = q * (1.f/128.f) - mu*mu;
            mu_s[r] = mu;
            rs_s[r] = rsqrtf(var + 1e-5f);
        }
    }
}

// Fused: h = silu(x@sageW + S1@aggW + b) + LN(X@valW * w);  out = LN(silu(h@linW + b2))
__global__ __launch_bounds__(256, 2) void k_fused(const float* __restrict__ x,
                                                  const float* __restrict__ sageB,
                                                  const float* __restrict__ lnG1,
                                                  const float* __restrict__ lnB1,
                                                  const float* __restrict__ linB,
                                                  const float* __restrict__ lnG2,
                                                  const float* __restrict__ lnB2,
                                                  float* __restrict__ out) {
    extern __shared__ __align__(16) char dsm[];
    float* Ws  = (float*)dsm;              // [3][64][WST] (A region)
    float* Vs2 = (float*)(dsm + BH_B);     // [64][VST]    (B region)
    float* Vs  = (float*)dsm;              // [64][VST]    (A region, final)
    __shared__ float w_s[64], mu_s[64], rs_s[64];
    int tid = threadIdx.x;
    size_t m0 = (size_t)blockIdx.x * 64;

    float acc1[2][4][4] = {};
    float acc2[2][4][4] = {};
    float aW0[2][4] = {};
    float aW1[2][4] = {};
    float aW2[2][4] = {};

    mma_stage<true>(x,    0, m0, tid, dsm, acc1, aW0);
    mma_stage<true>(g_S1, 1, m0, tid, dsm, acc1, aW1);
    mma_stage<true>(g_X,  2, m0, tid, dsm, acc2, aW2);

    __syncthreads();
    int lane = tid & 31, w = tid >> 5;
    int wm = w >> 2, wn = w & 3;
    int g = lane >> 2, tc = (lane & 3)*2;

    // retention weights via staged KQ products (A region)
    #pragma unroll
    for (int mf = 0; mf < 2; ++mf) {
        int r0 = wm*32 + mf*16 + g, r1 = r0 + 8;
        int c = wn*8 + tc;
        Ws[(      r0)*WST + c] = aW0[mf][0]; Ws[(      r0)*WST + c + 1] = aW0[mf][1];
        Ws[(      r1)*WST + c] = aW0[mf][2]; Ws[(      r1)*WST + c + 1] = aW0[mf][3];
        Ws[( 64 + r0)*WST + c] = aW1[mf][0]; Ws[( 64 + r0)*WST + c + 1] = aW1[mf][1];
        Ws[( 64 + r1)*WST + c] = aW1[mf][2]; Ws[( 64 + r1)*WST + c + 1] = aW1[mf][3];
        Ws[(128 + r0)*WST + c] = aW2[mf][0]; Ws[(128 + r0)*WST + c + 1] = aW2[mf][1];
        Ws[(128 + r1)*WST + c] = aW2[mf][2]; Ws[(128 + r1)*WST + c + 1] = aW2[mf][3];
    }
    __syncthreads();
    {
        int row = tid >> 2, part = tid & 3;
        float a = 0.f;
        #pragma unroll
        for (int j = 0; j < 4; ++j) {
            int k = part*4 + j;
            float pX = Ws[row*WST + k],             qX = Ws[row*WST + 16 + k];
            float pS = 0.5f*Ws[(64 + row)*WST + k], qS = 0.5f*Ws[(64 + row)*WST + 16 + k];
            float pG = Ws[(128 + row)*WST + k],     qG = Ws[(128 + row)*WST + 16 + k];
            float p2 = pG - pX - pS, q2 = qG - qX - qS;
            a += pX*qX + pS*qS + p2*q2;
        }
        a += __shfl_xor_sync(0xffffffffu, a, 1);
        a += __shfl_xor_sync(0xffffffffu, a, 2);
        if (part == 0) w_s[row] = a * (1.f/16.f);
    }
    __syncthreads();

    // attn-LN stats over acc2*w (B region staging)
    #pragma unroll
    for (int mf = 0; mf < 2; ++mf) {
        int r0 = wm*32 + mf*16 + g, r1 = r0 + 8;
        float w0 = w_s[r0], w1 = w_s[r1];
        #pragma unroll
        for (int nf = 0; nf < 4; ++nf) {
            int c = wn*32 + nf*8 + tc;
            *(float2*)&Vs2[r0*VST + c] = make_float2(acc2[mf][nf][0]*w0, acc2[mf][nf][1]*w0);
            *(float2*)&Vs2[r1*VST + c] = make_float2(acc2[mf][nf][2]*w1, acc2[mf][nf][3]*w1);
        }
    }
    __syncthreads();
    ln_stats(Vs2, mu_s, rs_s, tid);
    __syncthreads();

    // h tile -> Vs2 (fp32, B region)
    #pragma unroll
    for (int mf = 0; mf < 2; ++mf) {
        int r0 = wm*32 + mf*16 + g, r1 = r0 + 8;
        float w0 = w_s[r0], w1 = w_s[r1];
        float mu0 = mu_s[r0], rs0 = rs_s[r0];
        float mu1 = mu_s[r1], rs1 = rs_s[r1];
        #pragma unroll
        for (int nf = 0; nf < 4; ++nf) {
            int c = wn*32 + nf*8 + tc;
            float2 sb = *(const float2*)&sageB[c];
            float2 gg = *(const float2*)&lnG1[c];
            float2 b2 = *(const float2*)&lnB1[c];
            float o00 = silu_f(acc1[mf][nf][0] + sb.x) + (acc2[mf][nf][0]*w0 - mu0)*rs0*gg.x + b2.x;
            float o01 = silu_f(acc1[mf][nf][1] + sb.y) + (acc2[mf][nf][1]*w0 - mu0)*rs0*gg.y + b2.y;
            float o10 = silu_f(acc1[mf][nf][2] + sb.x) + (acc2[mf][nf][2]*w1 - mu1)*rs1*gg.x + b2.x;
            float o11 = silu_f(acc1[mf][nf][3] + sb.y) + (acc2[mf][nf][3]*w1 - mu1)*rs1*gg.y + b2.y;
            *(float2*)&Vs2[r0*VST + c] = make_float2(o00, o01);
            *(float2*)&Vs2[r1*VST + c] = make_float2(o10, o11);
        }
    }
    __syncthreads();

    // stage 4: convert h (smem fp32) -> Ah/Al bf16 (A region)
    {
        const float4* H4 = (const float4*)Vs2;
        __nv_bfloat16* Ah = (__nv_bfloat16*)(dsm + AH_B);
        __nv_bfloat16* Al = (__nv_bfloat16*)(dsm + AL_B);
        #pragma unroll
        for (int i = tid; i < 64*32; i += 256) {
            int r = i >> 5, c4 = i & 31;
            float4 v = H4[r*(VST/4) + c4];
            __nv_bfloat16 h0 = __float2bfloat16(v.x), h1 = __float2bfloat16(v.y);
            __nv_bfloat16 h2 = __float2bfloat16(v.z), h3 = __float2bfloat16(v.w);
            __nv_bfloat16 l0 = __float2bfloat16(v.x - __bfloat162float(h0));
            __nv_bfloat16 l1 = __float2bfloat16(v.y - __bfloat162float(h1));
            __nv_bfloat16 l2 = __float2bfloat16(v.z - __bfloat162float(h2));
            __nv_bfloat16 l3 = __float2bfloat16(v.w - __bfloat162float(h3));
            *(uint2*)&Ah[r*AST + c4*4] = make_uint2(pkbf(h0, h1), pkbf(h2, h3));
            *(uint2*)&Al[r*AST + c4*4] = make_uint2(pkbf(l0, l1), pkbf(l2, l3));
        }
    }
    __syncthreads();   // all h reads done before overwriting B region
    {
        const float4* srcH = (const float4*)(g_Wh + (size_t)3*WSZ);
        const float4* srcL = (const float4*)(g_Wl + (size_t)3*WSZ);
        float4* dH = (float4*)(dsm + BH_B);
        float4* dL = (float4*)(dsm + BL_B);
        #pragma unroll
        for (int i = tid; i < (128*BST)/8; i += 256) {
            dH[i] = srcH[i];
            dL[i] = srcL[i];
        }
    }
    __syncthreads();

    float acc3[2][4][4] = {};
    float aWd[2][4];
    mma_compute<false>(dsm, tid, acc3, aWd);
    __syncthreads();   // all fragment reads done before final staging overwrites A region

    // final: silu + LN -> out
    #pragma unroll
    for (int mf = 0; mf < 2; ++mf) {
        int r0 = wm*32 + mf*16 + g, r1 = r0 + 8;
        #pragma unroll
        for (int nf = 0; nf < 4; ++nf) {
            int c = wn*32 + nf*8 + tc;
            float2 bb = *(const float2*)&linB[c];
            acc3[mf][nf][0] = silu_f(acc3[mf][nf][0] + bb.x);
            acc3[mf][nf][1] = silu_f(acc3[mf][nf][1] + bb.y);
            acc3[mf][nf][2] = silu_f(acc3[mf][nf][2] + bb.x);
            acc3[mf][nf][3] = silu_f(acc3[mf][nf][3] + bb.y);
            *(float2*)&Vs[r0*VST + c] = make_float2(acc3[mf][nf][0], acc3[mf][nf][1]);
            *(float2*)&Vs[r1*VST + c] = make_float2(acc3[mf][nf][2], acc3[mf][nf][3]);
        }
    }
    __syncthreads();
    ln_stats(Vs, mu_s, rs_s, tid);
    __syncthreads();

    #pragma unroll
    for (int mf = 0; mf < 2; ++mf) {
        int r0 = wm*32 + mf*16 + g, r1 = r0 + 8;
        float mu0 = mu_s[r0], rs0 = rs_s[r0];
        float mu1 = mu_s[r1], rs1 = rs_s[r1];
        #pragma unroll
        for (int nf = 0; nf < 4; ++nf) {
            int c = wn*32 + nf*8 + tc;
            float2 gg = *(const float2*)&lnG2[c];
            float2 b2 = *(const float2*)&lnB2[c];
            float o00 = (acc3[mf][nf][0] - mu0)*rs0*gg.x + b2.x;
            float o01 = (acc3[mf][nf][1] - mu0)*rs0*gg.y + b2.y;
            float o10 = (acc3[mf][nf][2] - mu1)*rs1*gg.x + b2.x;
            float o11 = (acc3[mf][nf][3] - mu1)*rs1*gg.y + b2.y;
            *(float2*)&out[(m0 + r0)*(size_t)D + c] = make_float2(o00, o01);
            *(float2*)&out[(m0 + r1)*(size_t)D + c] = make_float2(o10, o11);
        }
    }
}

// ---------------- launch ----------------
extern "C" void kernel_launch(void* const* d_in, const int* in_sizes, int n_in,
                              void* d_out, int out_size) {
    const float* x         = (const float*)d_in[0];
    const int*   edge_rows = (const int*)  d_in[1];
    const int*   edge_cols = (const int*)  d_in[2];
    const float* edge_vals = (const float*)d_in[3];
    const float* sage_W    = (const float*)d_in[4];
    const float* sage_b    = (const float*)d_in[5];
    const float* sage_aggW = (const float*)d_in[6];
    const float* key_W     = (const float*)d_in[7];
    const float* query_W   = (const float*)d_in[8];
    const float* value_W   = (const float*)d_in[9];
    const float* attn_ln_g = (const float*)d_in[10];
    const float* attn_ln_b = (const float*)d_in[11];
    const float* lin_W     = (const float*)d_in[12];
    const float* lin_b     = (const float*)d_in[13];
    const float* ln_g      = (const float*)d_in[14];
    const float* ln_b      = (const float*)d_in[15];
    float* out = (float*)d_out;

    cudaFuncSetAttribute(k_fused, cudaFuncAttributeMaxDynamicSharedMemorySize, SMEM_GEMM);

    k_prepw<<<(PW_XH + 255)/256, 256>>>(sage_W, sage_aggW, value_W, lin_W,
                                        key_W, query_W, x);
    k_hist<<<(NE + 255)/256, 256>>>(edge_rows);
    k_scanA<<<20, 1024>>>();
    k_scanFix<<<(NN + 256)/256, 256>>>();
    k_scatter<<<(NE + 255)/256, 256>>>(edge_rows, edge_cols, edge_vals);

    k_spmm<<<NN, 128>>>(x, 0);
    k_spmm<<<NN, 128>>>(x, 1);

    // fully fused GEMM chain -> out
    k_fused<<<MROWS/64, 256, SMEM_GEMM>>>(x, sage_b, attn_ln_g, attn_ln_b,
                                          lin_b, ln_g, ln_b, out);
}

// round 13
// speedup vs baseline: 1.0074x; 1.0074x over previous
#include <cuda_runtime.h>
#include <cuda_bf16.h>
#include <math.h>
#include <stdint.h>

#define L 4
#define NN 40000
#define D 128
#define KD 16
#define NE 320000
#define MROWS (L*NN)                 // 160000
#define SLICE ((size_t)NN*(size_t)D)
#define VST 132                      // LN staging row stride (floats)
#define AST 136                      // A smem row stride (bf16 elems)
#define BST 136                      // B smem/global row stride (bf16 elems, n-major)
#define WSZ (128*BST)                // one converted weight matrix (bf16 elems)
#define WST 33                       // Ws staging row stride (floats)

// byte offsets inside dynamic smem (BM=128 tile)
#define AH_B 0
#define AL_B (128*AST*2)             // 34816
#define BH_B (2*128*AST*2)           // 69632
#define BL_B (BH_B + 128*BST*2)      // 104448
#define SMEM_GEMM (BL_B + 128*BST*2) // 139264

__device__ __forceinline__ unsigned pkbf(__nv_bfloat16 a, __nv_bfloat16 b) {
    __nv_bfloat162 t = __halves2bfloat162(a, b);
    return *(unsigned*)&t;
}

__device__ __forceinline__ void mma16816(float c[4], const unsigned a[4], const unsigned b[2]) {
    asm volatile("mma.sync.aligned.m16n8k16.row.col.f32.bf16.bf16.f32 "
        "{%0,%1,%2,%3},{%4,%5,%6,%7},{%8,%9},{%0,%1,%2,%3};"
        : "+f"(c[0]), "+f"(c[1]), "+f"(c[2]), "+f"(c[3])
        : "r"(a[0]), "r"(a[1]), "r"(a[2]), "r"(a[3]), "r"(b[0]), "r"(b[1]));
}

// ---------------- device scratch ----------------
static __device__ float g_S1[(size_t)L*NN*D];
static __device__ float g_X [(size_t)L*NN*D];
static __device__ int   g_rowptr[NN+1];
static __device__ int   g_cnt[NN];
static __device__ int   g_cur[NN];
static __device__ int   g_ecol[NE];
static __device__ float g_eval[NE];
static __device__ int   g_bsum[20];
// precomputed bf16 hi/lo weights, n-major [n*BST + k]; idx: 0=sage 1=agg 2=val 3=lin
static __device__ __align__(16) __nv_bfloat16 g_Wh[4*WSZ];
static __device__ __align__(16) __nv_bfloat16 g_Wl[4*WSZ];
// KQ = [Kw | Qw] bf16 hi/lo, n-major [n*128 + k]
static __device__ __align__(16) __nv_bfloat16 g_KQh[32*128];
static __device__ __align__(16) __nv_bfloat16 g_KQl[32*128];

// ---------------- prepw: weights+KQ bf16 hi/lo; zero CSR counters ----------------
__global__ __launch_bounds__(256) void k_prepw(const float* __restrict__ w0,
                                               const float* __restrict__ w1,
                                               const float* __restrict__ w2,
                                               const float* __restrict__ w3,
                                               const float* __restrict__ keyW,
                                               const float* __restrict__ qryW) {
    int idx = blockIdx.x*blockDim.x + threadIdx.x;
    if (idx < 4*128*128) {
        int m = idx >> 14, r = idx & 16383, k = r >> 7, n = r & 127;
        const float* W = (m == 0) ? w0 : (m == 1) ? w1 : (m == 2) ? w2 : w3;
        float v = W[k*D + n];
        __nv_bfloat16 h = __float2bfloat16(v);
        __nv_bfloat16 l = __float2bfloat16(v - __bfloat162float(h));
        g_Wh[m*WSZ + n*BST + k] = h;
        g_Wl[m*WSZ + n*BST + k] = l;
    } else if (idx < 4*128*128 + 32*128) {
        int r = idx - 4*128*128, n = r >> 7, k = r & 127;
        float v = (n < KD) ? keyW[k*KD + n] : qryW[k*KD + (n - KD)];
        __nv_bfloat16 h = __float2bfloat16(v);
        __nv_bfloat16 l = __float2bfloat16(v - __bfloat162float(h));
        g_KQh[n*128 + k] = h;
        g_KQl[n*128 + k] = l;
    } else if (idx < 4*128*128 + 32*128 + NN) {
        int i = idx - 4*128*128 - 32*128;
        g_cnt[i] = 0; g_cur[i] = 0;
    }
}

// ---------------- CSR build ----------------
__global__ void k_hist(const int* __restrict__ rows) {
    int e = blockIdx.x*blockDim.x + threadIdx.x;
    if (e < NE) atomicAdd(&g_cnt[rows[e]], 1);
}

__global__ __launch_bounds__(1024) void k_scanA() {
    __shared__ int wsum[32];
    int t = threadIdx.x, b = blockIdx.x;
    int i0 = b*2048 + 2*t;
    int a = (i0     < NN) ? g_cnt[i0]   : 0;
    int c = (i0 + 1 < NN) ? g_cnt[i0+1] : 0;
    int pair = a + c;
    int lane = t & 31, wid = t >> 5;
    int v = pair;
    #pragma unroll
    for (int o = 1; o < 32; o <<= 1) {
        int tt = __shfl_up_sync(0xffffffffu, v, o);
        if (lane >= o) v += tt;
    }
    if (lane == 31) wsum[wid] = v;
    __syncthreads();
    if (wid == 0) {
        int s = wsum[lane];
        #pragma unroll
        for (int o = 1; o < 32; o <<= 1) {
            int tt = __shfl_up_sync(0xffffffffu, s, o);
            if (lane >= o) s += tt;
        }
        wsum[lane] = s;
    }
    __syncthreads();
    int excl = v - pair + ((wid > 0) ? wsum[wid-1] : 0);
    if (i0     < NN) g_rowptr[i0]   = excl;
    if (i0 + 1 < NN) g_rowptr[i0+1] = excl + a;
    if (t == 1023) g_bsum[b] = excl + pair;
}

__global__ void k_scanFix() {
    int i = blockIdx.x*blockDim.x + threadIdx.x;
    if (i <= NN) {
        int b = (i < NN) ? (i >> 11) : 20;
        int off = 0;
        for (int j = 0; j < b; ++j) off += g_bsum[j];
        if (i < NN) g_rowptr[i] += off;
        else        g_rowptr[NN] = off;
    }
}

__global__ void k_scatter(const int* __restrict__ rows, const int* __restrict__ cols,
                          const float* __restrict__ vals) {
    int e = blockIdx.x*blockDim.x + threadIdx.x;
    if (e < NE) {
        int r = rows[e];
        int p = atomicAdd(&g_cur[r], 1);
        int idx = g_rowptr[r] + p;
        g_ecol[idx] = cols[e];
        g_eval[idx] = vals[e];
    }
}

// ---------------- SPMM (fp32 gather, 2-edge unroll — R11 proven) ----------------
__global__ __launch_bounds__(128) void k_spmm(const float* __restrict__ x, int stage) {
    const float* __restrict__ in = (stage == 0) ? x : (const float*)g_S1;
    int r = blockIdx.x;
    int d = threadIdx.x;
    int s  = g_rowptr[r];
    int e2 = g_rowptr[r+1];
    float a0 = 0.f, a1 = 0.f, a2 = 0.f, a3 = 0.f;
    int i = s;
    for (; i + 1 < e2; i += 2) {
        int   c0 = g_ecol[i],   c1 = g_ecol[i+1];
        float v0 = g_eval[i],   v1 = g_eval[i+1];
        const float* p0 = in + (size_t)c0*D + d;
        const float* p1 = in + (size_t)c1*D + d;
        float u0 = p0[0],        w0 = p1[0];
        float u1 = p0[SLICE],    w1 = p1[SLICE];
        float u2 = p0[2*SLICE],  w2 = p1[2*SLICE];
        float u3 = p0[3*SLICE],  w3 = p1[3*SLICE];
        a0 += v0*u0 + v1*w0;
        a1 += v0*u1 + v1*w1;
        a2 += v0*u2 + v1*w2;
        a3 += v0*u3 + v1*w3;
    }
    if (i < e2) {
        int   c = g_ecol[i];
        float v = g_eval[i];
        const float* p = in + (size_t)c*D + d;
        a0 += v * p[0];
        a1 += v * p[SLICE];
        a2 += v * p[2*SLICE];
        a3 += v * p[3*SLICE];
    }
    size_t o = (size_t)r*D + d;
    if (stage == 0) {
        g_S1[o]           = a0;
        g_S1[o +   SLICE] = a1;
        g_S1[o + 2*SLICE] = a2;
        g_S1[o + 3*SLICE] = a3;
    } else {
        g_X[o]         = x[o]         + 0.5f*in[o]         + 0.25f*a0;
        g_X[o+  SLICE] = x[o+  SLICE] + 0.5f*in[o+  SLICE] + 0.25f*a1;
        g_X[o+2*SLICE] = x[o+2*SLICE] + 0.5f*in[o+2*SLICE] + 0.25f*a2;
        g_X[o+3*SLICE] = x[o+3*SLICE] + 0.5f*in[o+3*SLICE] + 0.25f*a3;
    }
}

__device__ __forceinline__ float silu_f(float v) { return v / (1.f + expf(-v)); }

// inner MMA compute (BM=128, 16 warps 4m x 4n, warp tile 32x32), fragments hoisted per kk
template<bool WQ>
__device__ __forceinline__ void mma_compute(char* dsm, int tid,
                                            float acc[2][4][4], float accW[2][4]) {
    int lane = tid & 31, w = tid >> 5;
    int wm = w >> 2, wn = w & 3;
    int g = lane >> 2, tc = (lane & 3)*2;
    int ar = wm*32 + g;
    const __nv_bfloat16* Ah = (const __nv_bfloat16*)(dsm + AH_B);
    const __nv_bfloat16* Al = (const __nv_bfloat16*)(dsm + AL_B);
    const __nv_bfloat16* Bh = (const __nv_bfloat16*)(dsm + BH_B);
    const __nv_bfloat16* Bl = (const __nv_bfloat16*)(dsm + BL_B);
    #pragma unroll
    for (int kk = 0; kk < 8; ++kk) {
        int k0 = kk*16;
        unsigned aH[2][4], aL[2][4], bH[4][2], bL[4][2];
        #pragma unroll
        for (int mf = 0; mf < 2; ++mf) {
            const __nv_bfloat16* bh = Ah + (ar + mf*16)*AST + k0 + tc;
            const __nv_bfloat16* bl = Al + (ar + mf*16)*AST + k0 + tc;
            aH[mf][0] = *(const unsigned*)(bh);
            aH[mf][1] = *(const unsigned*)(bh + 8*AST);
            aH[mf][2] = *(const unsigned*)(bh + 8);
            aH[mf][3] = *(const unsigned*)(bh + 8*AST + 8);
            aL[mf][0] = *(const unsigned*)(bl);
            aL[mf][1] = *(const unsigned*)(bl + 8*AST);
            aL[mf][2] = *(const unsigned*)(bl + 8);
            aL[mf][3] = *(const unsigned*)(bl + 8*AST + 8);
        }
        #pragma unroll
        for (int nf = 0; nf < 4; ++nf) {
            const __nv_bfloat16* bh = Bh + (wn*32 + nf*8 + g)*BST + k0 + tc;
            const __nv_bfloat16* bl = Bl + (wn*32 + nf*8 + g)*BST + k0 + tc;
            bH[nf][0] = *(const unsigned*)(bh);
            bH[nf][1] = *(const unsigned*)(bh + 8);
            bL[nf][0] = *(const unsigned*)(bl);
            bL[nf][1] = *(const unsigned*)(bl + 8);
        }
        #pragma unroll
        for (int mf = 0; mf < 2; ++mf)
            #pragma unroll
            for (int nf = 0; nf < 4; ++nf) {
                mma16816(acc[mf][nf], aH[mf], bH[nf]);   // Ah@Bh
                mma16816(acc[mf][nf], aL[mf], bH[nf]);   // Al@Bh
                mma16816(acc[mf][nf], aH[mf], bL[nf]);   // Ah@Bl
            }
        if (WQ) {
            const __nv_bfloat16* kh = g_KQh + (wn*8 + g)*128 + k0 + tc;
            const __nv_bfloat16* kl = g_KQl + (wn*8 + g)*128 + k0 + tc;
            unsigned kqH[2], kqL[2];
            kqH[0] = *(const unsigned*)(kh);
            kqH[1] = *(const unsigned*)(kh + 8);
            kqL[0] = *(const unsigned*)(kl);
            kqL[1] = *(const unsigned*)(kl + 8);
            mma16816(accW[0], aH[0], kqH);
            mma16816(accW[1], aH[1], kqH);
            mma16816(accW[0], aL[0], kqH);
            mma16816(accW[1], aL[1], kqH);
            mma16816(accW[0], aH[0], kqL);
            mma16816(accW[1], aH[1], kqL);
        }
    }
}

// full stage with A from global fp32 (128-row tile, 512 threads)
template<bool WQ>
__device__ __forceinline__ void mma_stage(const float* __restrict__ Agl,
                                          int widx, size_t m0, int tid, char* dsm,
                                          float acc[2][4][4], float accW[2][4]) {
    __syncthreads();
    {
        const float4* A4 = (const float4*)Agl;
        __nv_bfloat16* Ah = (__nv_bfloat16*)(dsm + AH_B);
        __nv_bfloat16* Al = (__nv_bfloat16*)(dsm + AL_B);
        #pragma unroll
        for (int i = tid; i < 128*32; i += 512) {
            int r = i >> 5, c4 = i & 31;
            float4 v = A4[(m0 + r)*32 + c4];
            __nv_bfloat16 h0 = __float2bfloat16(v.x), h1 = __float2bfloat16(v.y);
            __nv_bfloat16 h2 = __float2bfloat16(v.z), h3 = __float2bfloat16(v.w);
            __nv_bfloat16 l0 = __float2bfloat16(v.x - __bfloat162float(h0));
            __nv_bfloat16 l1 = __float2bfloat16(v.y - __bfloat162float(h1));
            __nv_bfloat16 l2 = __float2bfloat16(v.z - __bfloat162float(h2));
            __nv_bfloat16 l3 = __float2bfloat16(v.w - __bfloat162float(h3));
            *(uint2*)&Ah[r*AST + c4*4] = make_uint2(pkbf(h0, h1), pkbf(h2, h3));
            *(uint2*)&Al[r*AST + c4*4] = make_uint2(pkbf(l0, l1), pkbf(l2, l3));
        }
        const float4* srcH = (const float4*)(g_Wh + (size_t)widx*WSZ);
        const float4* srcL = (const float4*)(g_Wl + (size_t)widx*WSZ);
        float4* dH = (float4*)(dsm + BH_B);
        float4* dL = (float4*)(dsm + BL_B);
        #pragma unroll
        for (int i = tid; i < (128*BST)/8; i += 512) {
            dH[i] = srcH[i];
            dL[i] = srcL[i];
        }
    }
    __syncthreads();
    mma_compute<WQ>(dsm, tid, acc, accW);
}

// shared LN row-stats: Vs[128][VST] -> mu_s, rs_s (16 warps)
__device__ __forceinline__ void ln_stats(const float* Vs, float* mu_s, float* rs_s, int tid) {
    int w = tid >> 5, lane = tid & 31;
    for (int r = w; r < 128; r += 16) {
        float s = 0.f, q = 0.f;
        #pragma unroll
        for (int c = lane; c < 128; c += 32) { float v = Vs[r*VST + c]; s += v; q += v*v; }
        #pragma unroll
        for (int o = 16; o > 0; o >>= 1) {
            s += __shfl_down_sync(0xffffffffu, s, o);
            q += __shfl_down_sync(0xffffffffu, q, o);
        }
        if (lane == 0) {
            float mu = s * (1.f/128.f);
            float var = q * (1.f/128.f) - mu*mu;
            mu_s[r] = mu;
            rs_s[r] = rsqrtf(var + 1e-5f);
        }
    }
}

// Fused: h = silu(x@sageW + S1@aggW + b) + LN(X@valW * w);  out = LN(silu(h@linW + b2))
__global__ __launch_bounds__(512, 1) void k_fused(const float* __restrict__ x,
                                                  const float* __restrict__ sageB,
                                                  const float* __restrict__ lnG1,
                                                  const float* __restrict__ lnB1,
                                                  const float* __restrict__ linB,
                                                  const float* __restrict__ lnG2,
                                                  const float* __restrict__ lnB2,
                                                  float* __restrict__ out) {
    extern __shared__ __align__(16) char dsm[];
    float* Ws  = (float*)dsm;              // [3][128][WST] (A region, 50688B <= 69632)
    float* Vs2 = (float*)(dsm + BH_B);     // [128][VST]    (B region, 67584B <= 69632)
    float* Vs  = (float*)dsm;              // [128][VST]    (A region, final)
    __shared__ float w_s[128], mu_s[128], rs_s[128];
    int tid = threadIdx.x;
    size_t m0 = (size_t)blockIdx.x * 128;

    float acc1[2][4][4] = {};
    float acc2[2][4][4] = {};
    float aW0[2][4] = {};
    float aW1[2][4] = {};
    float aW2[2][4] = {};

    mma_stage<true>(x,    0, m0, tid, dsm, acc1, aW0);
    mma_stage<true>(g_S1, 1, m0, tid, dsm, acc1, aW1);
    mma_stage<true>(g_X,  2, m0, tid, dsm, acc2, aW2);

    __syncthreads();
    int lane = tid & 31, w = tid >> 5;
    int wm = w >> 2, wn = w & 3;
    int g = lane >> 2, tc = (lane & 3)*2;

    // retention weights via staged KQ products (A region)
    #pragma unroll
    for (int mf = 0; mf < 2; ++mf) {
        int r0 = wm*32 + mf*16 + g, r1 = r0 + 8;
        int c = wn*8 + tc;
        Ws[(       r0)*WST + c] = aW0[mf][0]; Ws[(       r0)*WST + c + 1] = aW0[mf][1];
        Ws[(       r1)*WST + c] = aW0[mf][2]; Ws[(       r1)*WST + c + 1] = aW0[mf][3];
        Ws[(128 +  r0)*WST + c] = aW1[mf][0]; Ws[(128 +  r0)*WST + c + 1] = aW1[mf][1];
        Ws[(128 +  r1)*WST + c] = aW1[mf][2]; Ws[(128 +  r1)*WST + c + 1] = aW1[mf][3];
        Ws[(256 +  r0)*WST + c] = aW2[mf][0]; Ws[(256 +  r0)*WST + c + 1] = aW2[mf][1];
        Ws[(256 +  r1)*WST + c] = aW2[mf][2]; Ws[(256 +  r1)*WST + c + 1] = aW2[mf][3];
    }
    __syncthreads();
    {
        int row = tid >> 2, part = tid & 3;   // 512 threads -> 128 rows x 4 parts
        float a = 0.f;
        #pragma unroll
        for (int j = 0; j < 4; ++j) {
            int k = part*4 + j;
            float pX = Ws[row*WST + k],              qX = Ws[row*WST + 16 + k];
            float pS = 0.5f*Ws[(128 + row)*WST + k], qS = 0.5f*Ws[(128 + row)*WST + 16 + k];
            float pG = Ws[(256 + row)*WST + k],      qG = Ws[(256 + row)*WST + 16 + k];
            float p2 = pG - pX - pS, q2 = qG - qX - qS;
            a += pX*qX + pS*qS + p2*q2;
        }
        a += __shfl_xor_sync(0xffffffffu, a, 1);
        a += __shfl_xor_sync(0xffffffffu, a, 2);
        if (part == 0) w_s[row] = a * (1.f/16.f);
    }
    __syncthreads();

    // attn-LN stats over acc2*w (B region staging)
    #pragma unroll
    for (int mf = 0; mf < 2; ++mf) {
        int r0 = wm*32 + mf*16 + g, r1 = r0 + 8;
        float w0 = w_s[r0], w1 = w_s[r1];
        #pragma unroll
        for (int nf = 0; nf < 4; ++nf) {
            int c = wn*32 + nf*8 + tc;
            *(float2*)&Vs2[r0*VST + c] = make_float2(acc2[mf][nf][0]*w0, acc2[mf][nf][1]*w0);
            *(float2*)&Vs2[r1*VST + c] = make_float2(acc2[mf][nf][2]*w1, acc2[mf][nf][3]*w1);
        }
    }
    __syncthreads();
    ln_stats(Vs2, mu_s, rs_s, tid);
    __syncthreads();

    // h tile -> Vs2 (fp32, B region)
    #pragma unroll
    for (int mf = 0; mf < 2; ++mf) {
        int r0 = wm*32 + mf*16 + g, r1 = r0 + 8;
        float w0 = w_s[r0], w1 = w_s[r1];
        float mu0 = mu_s[r0], rs0 = rs_s[r0];
        float mu1 = mu_s[r1], rs1 = rs_s[r1];
        #pragma unroll
        for (int nf = 0; nf < 4; ++nf) {
            int c = wn*32 + nf*8 + tc;
            float2 sb = *(const float2*)&sageB[c];
            float2 gg = *(const float2*)&lnG1[c];
            float2 b2 = *(const float2*)&lnB1[c];
            float o00 = silu_f(acc1[mf][nf][0] + sb.x) + (acc2[mf][nf][0]*w0 - mu0)*rs0*gg.x + b2.x;
            float o01 = silu_f(acc1[mf][nf][1] + sb.y) + (acc2[mf][nf][1]*w0 - mu0)*rs0*gg.y + b2.y;
            float o10 = silu_f(acc1[mf][nf][2] + sb.x) + (acc2[mf][nf][2]*w1 - mu1)*rs1*gg.x + b2.x;
            float o11 = silu_f(acc1[mf][nf][3] + sb.y) + (acc2[mf][nf][3]*w1 - mu1)*rs1*gg.y + b2.y;
            *(float2*)&Vs2[r0*VST + c] = make_float2(o00, o01);
            *(float2*)&Vs2[r1*VST + c] = make_float2(o10, o11);
        }
    }
    __syncthreads();

    // stage 4: convert h (smem fp32) -> Ah/Al bf16 (A region)
    {
        const float4* H4 = (const float4*)Vs2;
        __nv_bfloat16* Ah = (__nv_bfloat16*)(dsm + AH_B);
        __nv_bfloat16* Al = (__nv_bfloat16*)(dsm + AL_B);
        #pragma unroll
        for (int i = tid; i < 128*32; i += 512) {
            int r = i >> 5, c4 = i & 31;
            float4 v = H4[r*(VST/4) + c4];
            __nv_bfloat16 h0 = __float2bfloat16(v.x), h1 = __float2bfloat16(v.y);
            __nv_bfloat16 h2 = __float2bfloat16(v.z), h3 = __float2bfloat16(v.w);
            __nv_bfloat16 l0 = __float2bfloat16(v.x - __bfloat162float(h0));
            __nv_bfloat16 l1 = __float2bfloat16(v.y - __bfloat162float(h1));
            __nv_bfloat16 l2 = __float2bfloat16(v.z - __bfloat162float(h2));
            __nv_bfloat16 l3 = __float2bfloat16(v.w - __bfloat162float(h3));
            *(uint2*)&Ah[r*AST + c4*4] = make_uint2(pkbf(h0, h1), pkbf(h2, h3));
            *(uint2*)&Al[r*AST + c4*4] = make_uint2(pkbf(l0, l1), pkbf(l2, l3));
        }
    }
    __syncthreads();   // all h reads done before overwriting B region
    {
        const float4* srcH = (const float4*)(g_Wh + (size_t)3*WSZ);
        const float4* srcL = (const float4*)(g_Wl + (size_t)3*WSZ);
        float4* dH = (float4*)(dsm + BH_B);
        float4* dL = (float4*)(dsm + BL_B);
        #pragma unroll
        for (int i = tid; i < (128*BST)/8; i += 512) {
            dH[i] = srcH[i];
            dL[i] = srcL[i];
        }
    }
    __syncthreads();

    float acc3[2][4][4] = {};
    float aWd[2][4];
    mma_compute<false>(dsm, tid, acc3, aWd);
    __syncthreads();   // all fragment reads done before final staging overwrites A region

    // final: silu + LN -> out
    #pragma unroll
    for (int mf = 0; mf < 2; ++mf) {
        int r0 = wm*32 + mf*16 + g, r1 = r0 + 8;
        #pragma unroll
        for (int nf = 0; nf < 4; ++nf) {
            int c = wn*32 + nf*8 + tc;
            float2 bb = *(const float2*)&linB[c];
            acc3[mf][nf][0] = silu_f(acc3[mf][nf][0] + bb.x);
            acc3[mf][nf][1] = silu_f(acc3[mf][nf][1] + bb.y);
            acc3[mf][nf][2] = silu_f(acc3[mf][nf][2] + bb.x);
            acc3[mf][nf][3] = silu_f(acc3[mf][nf][3] + bb.y);
            *(float2*)&Vs[r0*VST + c] = make_float2(acc3[mf][nf][0], acc3[mf][nf][1]);
            *(float2*)&Vs[r1*VST + c] = make_float2(acc3[mf][nf][2], acc3[mf][nf][3]);
        }
    }
    __syncthreads();
    ln_stats(Vs, mu_s, rs_s, tid);
    __syncthreads();

    #pragma unroll
    for (int mf = 0; mf < 2; ++mf) {
        int r0 = wm*32 + mf*16 + g, r1 = r0 + 8;
        float mu0 = mu_s[r0], rs0 = rs_s[r0];
        float mu1 = mu_s[r1], rs1 = rs_s[r1];
        #pragma unroll
        for (int nf = 0; nf < 4; ++nf) {
            int c = wn*32 + nf*8 + tc;
            float2 gg = *(const float2*)&lnG2[c];
            float2 b2 = *(const float2*)&lnB2[c];
            float o00 = (acc3[mf][nf][0] - mu0)*rs0*gg.x + b2.x;
            float o01 = (acc3[mf][nf][1] - mu0)*rs0*gg.y + b2.y;
            float o10 = (acc3[mf][nf][2] - mu1)*rs1*gg.x + b2.x;
            float o11 = (acc3[mf][nf][3] - mu1)*rs1*gg.y + b2.y;
            *(float2*)&out[(m0 + r0)*(size_t)D + c] = make_float2(o00, o01);
            *(float2*)&out[(m0 + r1)*(size_t)D + c] = make_float2(o10, o11);
        }
    }
}

// ---------------- launch ----------------
extern "C" void kernel_launch(void* const* d_in, const int* in_sizes, int n_in,
                              void* d_out, int out_size) {
    const float* x         = (const float*)d_in[0];
    const int*   edge_rows = (const int*)  d_in[1];
    const int*   edge_cols = (const int*)  d_in[2];
    const float* edge_vals = (const float*)d_in[3];
    const float* sage_W    = (const float*)d_in[4];
    const float* sage_b    = (const float*)d_in[5];
    const float* sage_aggW = (const float*)d_in[6];
    const float* key_W     = (const float*)d_in[7];
    const float* query_W   = (const float*)d_in[8];
    const float* value_W   = (const float*)d_in[9];
    const float* attn_ln_g = (const float*)d_in[10];
    const float* attn_ln_b = (const float*)d_in[11];
    const float* lin_W     = (const float*)d_in[12];
    const float* lin_b     = (const float*)d_in[13];
    const float* ln_g      = (const float*)d_in[14];
    const float* ln_b      = (const float*)d_in[15];
    float* out = (float*)d_out;

    cudaFuncSetAttribute(k_fused, cudaFuncAttributeMaxDynamicSharedMemorySize, SMEM_GEMM);

    k_prepw<<<(4*128*128 + 32*128 + NN + 255)/256, 256>>>(sage_W, sage_aggW, value_W, lin_W,
                                                          key_W, query_W);
    k_hist<<<(NE + 255)/256, 256>>>(edge_rows);
    k_scanA<<<20, 1024>>>();
    k_scanFix<<<(NN + 256)/256, 256>>>();
    k_scatter<<<(NE + 255)/256, 256>>>(edge_rows, edge_cols, edge_vals);

    k_spmm<<<NN, 128>>>(x, 0);
    k_spmm<<<NN, 128>>>(x, 1);

    // fully fused GEMM chain -> out (BM=128, 512 threads)
    k_fused<<<MROWS/128, 512, SMEM_GEMM>>>(x, sage_b, attn_ln_g, attn_ln_b,
                                           lin_b, ln_g, ln_b, out);
}

// round 14
// speedup vs baseline: 1.0849x; 1.0769x over previous
#include <cuda_runtime.h>
#include <cuda_bf16.h>
#include <math.h>
#include <stdint.h>

#define L 4
#define NN 40000
#define D 128
#define KD 16
#define NE 320000
#define MROWS (L*NN)                 // 160000
#define SLICE ((size_t)NN*(size_t)D)
#define VST 132                      // LN staging row stride (floats)
#define AST 136                      // A smem row stride (bf16 elems)
#define BST 136                      // B smem/global row stride (bf16 elems, n-major)
#define WSZ (128*BST)                // one converted weight matrix (bf16 elems)
#define WST 33                       // Ws staging row stride (floats)

// byte offsets inside dynamic smem (BM=64 tile — R11 proven)
#define AH_B 0
#define AL_B (64*AST*2)              // 17408
#define BH_B (2*64*AST*2)            // 34816
#define BL_B (BH_B + 128*BST*2)      // 69632
#define SMEM_GEMM (BL_B + 128*BST*2) // 104448

__device__ __forceinline__ unsigned pkbf(__nv_bfloat16 a, __nv_bfloat16 b) {
    __nv_bfloat162 t = __halves2bfloat162(a, b);
    return *(unsigned*)&t;
}

__device__ __forceinline__ void mma16816(float c[4], const unsigned a[4], const unsigned b[2]) {
    asm volatile("mma.sync.aligned.m16n8k16.row.col.f32.bf16.bf16.f32 "
        "{%0,%1,%2,%3},{%4,%5,%6,%7},{%8,%9},{%0,%1,%2,%3};"
        : "+f"(c[0]), "+f"(c[1]), "+f"(c[2]), "+f"(c[3])
        : "r"(a[0]), "r"(a[1]), "r"(a[2]), "r"(a[3]), "r"(b[0]), "r"(b[1]));
}

// ---------------- device scratch ----------------
static __device__ float g_S1[(size_t)L*NN*D];
static __device__ float g_X [(size_t)L*NN*D];
static __device__ int   g_rowptr[NN+1];
static __device__ int   g_cnt[NN];
static __device__ int   g_cur[NN];
static __device__ int   g_ecol[NE];
static __device__ float g_eval[NE];
static __device__ int   g_bsum[20];
// precomputed bf16 hi/lo weights, n-major [n*BST + k]; idx: 0=sage 1=agg 2=val 3=lin
static __device__ __align__(16) __nv_bfloat16 g_Wh[4*WSZ];
static __device__ __align__(16) __nv_bfloat16 g_Wl[4*WSZ];
// KQ = [Kw | Qw] bf16 hi/lo, n-major [n*128 + k]
static __device__ __align__(16) __nv_bfloat16 g_KQh[32*128];
static __device__ __align__(16) __nv_bfloat16 g_KQl[32*128];

// ---------------- prepw: weights+KQ bf16 hi/lo; zero CSR counters ----------------
__global__ __launch_bounds__(256) void k_prepw(const float* __restrict__ w0,
                                               const float* __restrict__ w1,
                                               const float* __restrict__ w2,
                                               const float* __restrict__ w3,
                                               const float* __restrict__ keyW,
                                               const float* __restrict__ qryW) {
    int idx = blockIdx.x*blockDim.x + threadIdx.x;
    if (idx < 4*128*128) {
        int m = idx >> 14, r = idx & 16383, k = r >> 7, n = r & 127;
        const float* W = (m == 0) ? w0 : (m == 1) ? w1 : (m == 2) ? w2 : w3;
        float v = W[k*D + n];
        __nv_bfloat16 h = __float2bfloat16(v);
        __nv_bfloat16 l = __float2bfloat16(v - __bfloat162float(h));
        g_Wh[m*WSZ + n*BST + k] = h;
        g_Wl[m*WSZ + n*BST + k] = l;
    } else if (idx < 4*128*128 + 32*128) {
        int r = idx - 4*128*128, n = r >> 7, k = r & 127;
        float v = (n < KD) ? keyW[k*KD + n] : qryW[k*KD + (n - KD)];
        __nv_bfloat16 h = __float2bfloat16(v);
        __nv_bfloat16 l = __float2bfloat16(v - __bfloat162float(h));
        g_KQh[n*128 + k] = h;
        g_KQl[n*128 + k] = l;
    } else if (idx < 4*128*128 + 32*128 + NN) {
        int i = idx - 4*128*128 - 32*128;
        g_cnt[i] = 0; g_cur[i] = 0;
    }
}

// ---------------- CSR build ----------------
__global__ void k_hist(const int* __restrict__ rows) {
    int e = blockIdx.x*blockDim.x + threadIdx.x;
    if (e < NE) atomicAdd(&g_cnt[rows[e]], 1);
}

__global__ __launch_bounds__(1024) void k_scanA() {
    __shared__ int wsum[32];
    int t = threadIdx.x, b = blockIdx.x;
    int i0 = b*2048 + 2*t;
    int a = (i0     < NN) ? g_cnt[i0]   : 0;
    int c = (i0 + 1 < NN) ? g_cnt[i0+1] : 0;
    int pair = a + c;
    int lane = t & 31, wid = t >> 5;
    int v = pair;
    #pragma unroll
    for (int o = 1; o < 32; o <<= 1) {
        int tt = __shfl_up_sync(0xffffffffu, v, o);
        if (lane >= o) v += tt;
    }
    if (lane == 31) wsum[wid] = v;
    __syncthreads();
    if (wid == 0) {
        int s = wsum[lane];
        #pragma unroll
        for (int o = 1; o < 32; o <<= 1) {
            int tt = __shfl_up_sync(0xffffffffu, s, o);
            if (lane >= o) s += tt;
        }
        wsum[lane] = s;
    }
    __syncthreads();
    int excl = v - pair + ((wid > 0) ? wsum[wid-1] : 0);
    if (i0     < NN) g_rowptr[i0]   = excl;
    if (i0 + 1 < NN) g_rowptr[i0+1] = excl + a;
    if (t == 1023) g_bsum[b] = excl + pair;
}

__global__ void k_scanFix() {
    int i = blockIdx.x*blockDim.x + threadIdx.x;
    if (i <= NN) {
        int b = (i < NN) ? (i >> 11) : 20;
        int off = 0;
        for (int j = 0; j < b; ++j) off += g_bsum[j];
        if (i < NN) g_rowptr[i] += off;
        else        g_rowptr[NN] = off;
    }
}

__global__ void k_scatter(const int* __restrict__ rows, const int* __restrict__ cols,
                          const float* __restrict__ vals) {
    int e = blockIdx.x*blockDim.x + threadIdx.x;
    if (e < NE) {
        int r = rows[e];
        int p = atomicAdd(&g_cur[r], 1);
        int idx = g_rowptr[r] + p;
        g_ecol[idx] = cols[e];
        g_eval[idx] = vals[e];
    }
}

// ---------------- SPMM (float4 gather: thread = (slice, col4); 4x fewer LDG issues) ----------------
__global__ __launch_bounds__(128) void k_spmm(const float* __restrict__ x, int stage) {
    const float* __restrict__ in = (stage == 0) ? x : (const float*)g_S1;
    int r  = blockIdx.x;
    int t  = threadIdx.x;
    int sl = t >> 5;          // slice 0..3
    int c4 = t & 31;          // float4 column
    const float4* in4 = (const float4*)(in + (size_t)sl*SLICE);
    int i0 = g_rowptr[r], i1 = g_rowptr[r+1];
    float4 a = make_float4(0.f, 0.f, 0.f, 0.f);
    int i = i0;
    for (; i + 1 < i1; i += 2) {
        int   c0 = g_ecol[i],  c1 = g_ecol[i+1];
        float v0 = g_eval[i],  v1 = g_eval[i+1];
        float4 u = in4[(size_t)c0*32 + c4];
        float4 w = in4[(size_t)c1*32 + c4];
        a.x += v0*u.x + v1*w.x;
        a.y += v0*u.y + v1*w.y;
        a.z += v0*u.z + v1*w.z;
        a.w += v0*u.w + v1*w.w;
    }
    if (i < i1) {
        int   c = g_ecol[i];
        float v = g_eval[i];
        float4 u = in4[(size_t)c*32 + c4];
        a.x += v*u.x; a.y += v*u.y; a.z += v*u.z; a.w += v*u.w;
    }
    size_t o4 = (size_t)r*32 + c4;
    if (stage == 0) {
        ((float4*)(g_S1 + (size_t)sl*SLICE))[o4] = a;
    } else {
        float4 xx = ((const float4*)(x + (size_t)sl*SLICE))[o4];
        float4 ss = in4[o4];   // S1
        float4 gx;
        gx.x = xx.x + 0.5f*ss.x + 0.25f*a.x;
        gx.y = xx.y + 0.5f*ss.y + 0.25f*a.y;
        gx.z = xx.z + 0.5f*ss.z + 0.25f*a.z;
        gx.w = xx.w + 0.5f*ss.w + 0.25f*a.w;
        ((float4*)(g_X + (size_t)sl*SLICE))[o4] = gx;
    }
}

__device__ __forceinline__ float silu_f(float v) { return v / (1.f + expf(-v)); }

// inner MMA compute: k-step outer, split-passes inner — fragments loaded ONCE per kk
template<bool WQ>
__device__ __forceinline__ void mma_compute(char* dsm, int tid,
                                            float acc[2][4][4], float accW[2][4]) {
    int lane = tid & 31, w = tid >> 5;
    int wm = w >> 2, wn = w & 3;
    int g = lane >> 2, tc = (lane & 3)*2;
    int ar = wm*32 + g;
    const __nv_bfloat16* Ah = (const __nv_bfloat16*)(dsm + AH_B);
    const __nv_bfloat16* Al = (const __nv_bfloat16*)(dsm + AL_B);
    const __nv_bfloat16* Bh = (const __nv_bfloat16*)(dsm + BH_B);
    const __nv_bfloat16* Bl = (const __nv_bfloat16*)(dsm + BL_B);
    #pragma unroll
    for (int kk = 0; kk < 8; ++kk) {
        int k0 = kk*16;
        unsigned aH[2][4], aL[2][4], bH[4][2], bL[4][2];
        #pragma unroll
        for (int mf = 0; mf < 2; ++mf) {
            const __nv_bfloat16* bh = Ah + (ar + mf*16)*AST + k0 + tc;
            const __nv_bfloat16* bl = Al + (ar + mf*16)*AST + k0 + tc;
            aH[mf][0] = *(const unsigned*)(bh);
            aH[mf][1] = *(const unsigned*)(bh + 8*AST);
            aH[mf][2] = *(const unsigned*)(bh + 8);
            aH[mf][3] = *(const unsigned*)(bh + 8*AST + 8);
            aL[mf][0] = *(const unsigned*)(bl);
            aL[mf][1] = *(const unsigned*)(bl + 8*AST);
            aL[mf][2] = *(const unsigned*)(bl + 8);
            aL[mf][3] = *(const unsigned*)(bl + 8*AST + 8);
        }
        #pragma unroll
        for (int nf = 0; nf < 4; ++nf) {
            const __nv_bfloat16* bh = Bh + (wn*32 + nf*8 + g)*BST + k0 + tc;
            const __nv_bfloat16* bl = Bl + (wn*32 + nf*8 + g)*BST + k0 + tc;
            bH[nf][0] = *(const unsigned*)(bh);
            bH[nf][1] = *(const unsigned*)(bh + 8);
            bL[nf][0] = *(const unsigned*)(bl);
            bL[nf][1] = *(const unsigned*)(bl + 8);
        }
        #pragma unroll
        for (int mf = 0; mf < 2; ++mf)
            #pragma unroll
            for (int nf = 0; nf < 4; ++nf) {
                mma16816(acc[mf][nf], aH[mf], bH[nf]);   // Ah@Bh
                mma16816(acc[mf][nf], aL[mf], bH[nf]);   // Al@Bh
                mma16816(acc[mf][nf], aH[mf], bL[nf]);   // Ah@Bl
            }
        if (WQ) {
            const __nv_bfloat16* kh = g_KQh + (wn*8 + g)*128 + k0 + tc;
            const __nv_bfloat16* kl = g_KQl + (wn*8 + g)*128 + k0 + tc;
            unsigned kqH[2], kqL[2];
            kqH[0] = *(const unsigned*)(kh);
            kqH[1] = *(const unsigned*)(kh + 8);
            kqL[0] = *(const unsigned*)(kl);
            kqL[1] = *(const unsigned*)(kl + 8);
            mma16816(accW[0], aH[0], kqH);
            mma16816(accW[1], aH[1], kqH);
            mma16816(accW[0], aL[0], kqH);
            mma16816(accW[1], aL[1], kqH);
            mma16816(accW[0], aH[0], kqL);
            mma16816(accW[1], aH[1], kqL);
        }
    }
}

// full stage with A from global fp32
template<bool WQ>
__device__ __forceinline__ void mma_stage(const float* __restrict__ Agl,
                                          int widx, size_t m0, int tid, char* dsm,
                                          float acc[2][4][4], float accW[2][4]) {
    __syncthreads();
    {
        const float4* A4 = (const float4*)Agl;
        __nv_bfloat16* Ah = (__nv_bfloat16*)(dsm + AH_B);
        __nv_bfloat16* Al = (__nv_bfloat16*)(dsm + AL_B);
        #pragma unroll
        for (int i = tid; i < 64*32; i += 256) {
            int r = i >> 5, c4 = i & 31;
            float4 v = A4[(m0 + r)*32 + c4];
            __nv_bfloat16 h0 = __float2bfloat16(v.x), h1 = __float2bfloat16(v.y);
            __nv_bfloat16 h2 = __float2bfloat16(v.z), h3 = __float2bfloat16(v.w);
            __nv_bfloat16 l0 = __float2bfloat16(v.x - __bfloat162float(h0));
            __nv_bfloat16 l1 = __float2bfloat16(v.y - __bfloat162float(h1));
            __nv_bfloat16 l2 = __float2bfloat16(v.z - __bfloat162float(h2));
            __nv_bfloat16 l3 = __float2bfloat16(v.w - __bfloat162float(h3));
            *(uint2*)&Ah[r*AST + c4*4] = make_uint2(pkbf(h0, h1), pkbf(h2, h3));
            *(uint2*)&Al[r*AST + c4*4] = make_uint2(pkbf(l0, l1), pkbf(l2, l3));
        }
        const float4* srcH = (const float4*)(g_Wh + (size_t)widx*WSZ);
        const float4* srcL = (const float4*)(g_Wl + (size_t)widx*WSZ);
        float4* dH = (float4*)(dsm + BH_B);
        float4* dL = (float4*)(dsm + BL_B);
        #pragma unroll
        for (int i = tid; i < (128*BST)/8; i += 256) {
            dH[i] = srcH[i];
            dL[i] = srcL[i];
        }
    }
    __syncthreads();
    mma_compute<WQ>(dsm, tid, acc, accW);
}

// shared LN row-stats: Vs[64][VST] -> mu_s, rs_s
__device__ __forceinline__ void ln_stats(const float* Vs, float* mu_s, float* rs_s, int tid) {
    int w = tid >> 5, lane = tid & 31;
    for (int r = w; r < 64; r += 8) {
        float s = 0.f, q = 0.f;
        #pragma unroll
        for (int c = lane; c < 128; c += 32) { float v = Vs[r*VST + c]; s += v; q += v*v; }
        #pragma unroll
        for (int o = 16; o > 0; o >>= 1) {
            s += __shfl_down_sync(0xffffffffu, s, o);
            q += __shfl_down_sync(0xffffffffu, q, o);
        }
        if (lane == 0) {
            float mu = s * (1.f/128.f);
            float var = q * (1.f/128.f) - mu*mu;
            mu_s[r] = mu;
            rs_s[r] = rsqrtf(var + 1e-5f);
        }
    }
}

// Fused: h = silu(x@sageW + S1@aggW + b) + LN(X@valW * w);  out = LN(silu(h@linW + b2))
__global__ __launch_bounds__(256, 2) void k_fused(const float* __restrict__ x,
                                                  const float* __restrict__ sageB,
                                                  const float* __restrict__ lnG1,
                                                  const float* __restrict__ lnB1,
                                                  const float* __restrict__ linB,
                                                  const float* __restrict__ lnG2,
                                                  const float* __restrict__ lnB2,
                                                  float* __restrict__ out) {
    extern __shared__ __align__(16) char dsm[];
    float* Ws  = (float*)dsm;              // [3][64][WST] (A region)
    float* Vs2 = (float*)(dsm + BH_B);     // [64][VST]    (B region)
    float* Vs  = (float*)dsm;              // [64][VST]    (A region, final)
    __shared__ float w_s[64], mu_s[64], rs_s[64];
    int tid = threadIdx.x;
    size_t m0 = (size_t)blockIdx.x * 64;

    float acc1[2][4][4] = {};
    float acc2[2][4][4] = {};
    float aW0[2][4] = {};
    float aW1[2][4] = {};
    float aW2[2][4] = {};

    mma_stage<true>(x,    0, m0, tid, dsm, acc1, aW0);
    mma_stage<true>(g_S1, 1, m0, tid, dsm, acc1, aW1);
    mma_stage<true>(g_X,  2, m0, tid, dsm, acc2, aW2);

    __syncthreads();
    int lane = tid & 31, w = tid >> 5;
    int wm = w >> 2, wn = w & 3;
    int g = lane >> 2, tc = (lane & 3)*2;

    // retention weights via staged KQ products (A region)
    #pragma unroll
    for (int mf = 0; mf < 2; ++mf) {
        int r0 = wm*32 + mf*16 + g, r1 = r0 + 8;
        int c = wn*8 + tc;
        Ws[(      r0)*WST + c] = aW0[mf][0]; Ws[(      r0)*WST + c + 1] = aW0[mf][1];
        Ws[(      r1)*WST + c] = aW0[mf][2]; Ws[(      r1)*WST + c + 1] = aW0[mf][3];
        Ws[( 64 + r0)*WST + c] = aW1[mf][0]; Ws[( 64 + r0)*WST + c + 1] = aW1[mf][1];
        Ws[( 64 + r1)*WST + c] = aW1[mf][2]; Ws[( 64 + r1)*WST + c + 1] = aW1[mf][3];
        Ws[(128 + r0)*WST + c] = aW2[mf][0]; Ws[(128 + r0)*WST + c + 1] = aW2[mf][1];
        Ws[(128 + r1)*WST + c] = aW2[mf][2]; Ws[(128 + r1)*WST + c + 1] = aW2[mf][3];
    }
    __syncthreads();
    {
        int row = tid >> 2, part = tid & 3;
        float a = 0.f;
        #pragma unroll
        for (int j = 0; j < 4; ++j) {
            int k = part*4 + j;
            float pX = Ws[row*WST + k],             qX = Ws[row*WST + 16 + k];
            float pS = 0.5f*Ws[(64 + row)*WST + k], qS = 0.5f*Ws[(64 + row)*WST + 16 + k];
            float pG = Ws[(128 + row)*WST + k],     qG = Ws[(128 + row)*WST + 16 + k];
            float p2 = pG - pX - pS, q2 = qG - qX - qS;
            a += pX*qX + pS*qS + p2*q2;
        }
        a += __shfl_xor_sync(0xffffffffu, a, 1);
        a += __shfl_xor_sync(0xffffffffu, a, 2);
        if (part == 0) w_s[row] = a * (1.f/16.f);
    }
    __syncthreads();

    // attn-LN stats over acc2*w (B region staging)
    #pragma unroll
    for (int mf = 0; mf < 2; ++mf) {
        int r0 = wm*32 + mf*16 + g, r1 = r0 + 8;
        float w0 = w_s[r0], w1 = w_s[r1];
        #pragma unroll
        for (int nf = 0; nf < 4; ++nf) {
            int c = wn*32 + nf*8 + tc;
            *(float2*)&Vs2[r0*VST + c] = make_float2(acc2[mf][nf][0]*w0, acc2[mf][nf][1]*w0);
            *(float2*)&Vs2[r1*VST + c] = make_float2(acc2[mf][nf][2]*w1, acc2[mf][nf][3]*w1);
        }
    }
    __syncthreads();
    ln_stats(Vs2, mu_s, rs_s, tid);
    __syncthreads();

    // h tile -> Vs2 (fp32, B region)
    #pragma unroll
    for (int mf = 0; mf < 2; ++mf) {
        int r0 = wm*32 + mf*16 + g, r1 = r0 + 8;
        float w0 = w_s[r0], w1 = w_s[r1];
        float mu0 = mu_s[r0], rs0 = rs_s[r0];
        float mu1 = mu_s[r1], rs1 = rs_s[r1];
        #pragma unroll
        for (int nf = 0; nf < 4; ++nf) {
            int c = wn*32 + nf*8 + tc;
            float2 sb = *(const float2*)&sageB[c];
            float2 gg = *(const float2*)&lnG1[c];
            float2 b2 = *(const float2*)&lnB1[c];
            float o00 = silu_f(acc1[mf][nf][0] + sb.x) + (acc2[mf][nf][0]*w0 - mu0)*rs0*gg.x + b2.x;
            float o01 = silu_f(acc1[mf][nf][1] + sb.y) + (acc2[mf][nf][1]*w0 - mu0)*rs0*gg.y + b2.y;
            float o10 = silu_f(acc1[mf][nf][2] + sb.x) + (acc2[mf][nf][2]*w1 - mu1)*rs1*gg.x + b2.x;
            float o11 = silu_f(acc1[mf][nf][3] + sb.y) + (acc2[mf][nf][3]*w1 - mu1)*rs1*gg.y + b2.y;
            *(float2*)&Vs2[r0*VST + c] = make_float2(o00, o01);
            *(float2*)&Vs2[r1*VST + c] = make_float2(o10, o11);
        }
    }
    __syncthreads();

    // stage 4: convert h (smem fp32) -> Ah/Al bf16 (A region)
    {
        const float4* H4 = (const float4*)Vs2;
        __nv_bfloat16* Ah = (__nv_bfloat16*)(dsm + AH_B);
        __nv_bfloat16* Al = (__nv_bfloat16*)(dsm + AL_B);
        #pragma unroll
        for (int i = tid; i < 64*32; i += 256) {
            int r = i >> 5, c4 = i & 31;
            float4 v = H4[r*(VST/4) + c4];
            __nv_bfloat16 h0 = __float2bfloat16(v.x), h1 = __float2bfloat16(v.y);
            __nv_bfloat16 h2 = __float2bfloat16(v.z), h3 = __float2bfloat16(v.w);
            __nv_bfloat16 l0 = __float2bfloat16(v.x - __bfloat162float(h0));
            __nv_bfloat16 l1 = __float2bfloat16(v.y - __bfloat162float(h1));
            __nv_bfloat16 l2 = __float2bfloat16(v.z - __bfloat162float(h2));
            __nv_bfloat16 l3 = __float2bfloat16(v.w - __bfloat162float(h3));
            *(uint2*)&Ah[r*AST + c4*4] = make_uint2(pkbf(h0, h1), pkbf(h2, h3));
            *(uint2*)&Al[r*AST + c4*4] = make_uint2(pkbf(l0, l1), pkbf(l2, l3));
        }
    }
    __syncthreads();   // all h reads done before overwriting B region
    {
        const float4* srcH = (const float4*)(g_Wh + (size_t)3*WSZ);
        const float4* srcL = (const float4*)(g_Wl + (size_t)3*WSZ);
        float4* dH = (float4*)(dsm + BH_B);
        float4* dL = (float4*)(dsm + BL_B);
        #pragma unroll
        for (int i = tid; i < (128*BST)/8; i += 256) {
            dH[i] = srcH[i];
            dL[i] = srcL[i];
        }
    }
    __syncthreads();

    float acc3[2][4][4] = {};
    float aWd[2][4];
    mma_compute<false>(dsm, tid, acc3, aWd);
    __syncthreads();   // all fragment reads done before final staging overwrites A region

    // final: silu + LN -> out
    #pragma unroll
    for (int mf = 0; mf < 2; ++mf) {
        int r0 = wm*32 + mf*16 + g, r1 = r0 + 8;
        #pragma unroll
        for (int nf = 0; nf < 4; ++nf) {
            int c = wn*32 + nf*8 + tc;
            float2 bb = *(const float2*)&linB[c];
            acc3[mf][nf][0] = silu_f(acc3[mf][nf][0] + bb.x);
            acc3[mf][nf][1] = silu_f(acc3[mf][nf][1] + bb.y);
            acc3[mf][nf][2] = silu_f(acc3[mf][nf][2] + bb.x);
            acc3[mf][nf][3] = silu_f(acc3[mf][nf][3] + bb.y);
            *(float2*)&Vs[r0*VST + c] = make_float2(acc3[mf][nf][0], acc3[mf][nf][1]);
            *(float2*)&Vs[r1*VST + c] = make_float2(acc3[mf][nf][2], acc3[mf][nf][3]);
        }
    }
    __syncthreads();
    ln_stats(Vs, mu_s, rs_s, tid);
    __syncthreads();

    #pragma unroll
    for (int mf = 0; mf < 2; ++mf) {
        int r0 = wm*32 + mf*16 + g, r1 = r0 + 8;
        float mu0 = mu_s[r0], rs0 = rs_s[r0];
        float mu1 = mu_s[r1], rs1 = rs_s[r1];
        #pragma unroll
        for (int nf = 0; nf < 4; ++nf) {
            int c = wn*32 + nf*8 + tc;
            float2 gg = *(const float2*)&lnG2[c];
            float2 b2 = *(const float2*)&lnB2[c];
            float o00 = (acc3[mf][nf][0] - mu0)*rs0*gg.x + b2.x;
            float o01 = (acc3[mf][nf][1] - mu0)*rs0*gg.y + b2.y;
            float o10 = (acc3[mf][nf][2] - mu1)*rs1*gg.x + b2.x;
            float o11 = (acc3[mf][nf][3] - mu1)*rs1*gg.y + b2.y;
            *(float2*)&out[(m0 + r0)*(size_t)D + c] = make_float2(o00, o01);
            *(float2*)&out[(m0 + r1)*(size_t)D + c] = make_float2(o10, o11);
        }
    }
}

// ---------------- launch ----------------
extern "C" void kernel_launch(void* const* d_in, const int* in_sizes, int n_in,
                              void* d_out, int out_size) {
    const float* x         = (const float*)d_in[0];
    const int*   edge_rows = (const int*)  d_in[1];
    const int*   edge_cols = (const int*)  d_in[2];
    const float* edge_vals = (const float*)d_in[3];
    const float* sage_W    = (const float*)d_in[4];
    const float* sage_b    = (const float*)d_in[5];
    const float* sage_aggW = (const float*)d_in[6];
    const float* key_W     = (const float*)d_in[7];
    const float* query_W   = (const float*)d_in[8];
    const float* value_W   = (const float*)d_in[9];
    const float* attn_ln_g = (const float*)d_in[10];
    const float* attn_ln_b = (const float*)d_in[11];
    const float* lin_W     = (const float*)d_in[12];
    const float* lin_b     = (const float*)d_in[13];
    const float* ln_g      = (const float*)d_in[14];
    const float* ln_b      = (const float*)d_in[15];
    float* out = (float*)d_out;

    cudaFuncSetAttribute(k_fused, cudaFuncAttributeMaxDynamicSharedMemorySize, SMEM_GEMM);

    k_prepw<<<(4*128*128 + 32*128 + NN + 255)/256, 256>>>(sage_W, sage_aggW, value_W, lin_W,
                                                          key_W, query_W);
    k_hist<<<(NE + 255)/256, 256>>>(edge_rows);
    k_scanA<<<20, 1024>>>();
    k_scanFix<<<(NN + 256)/256, 256>>>();
    k_scatter<<<(NE + 255)/256, 256>>>(edge_rows, edge_cols, edge_vals);

    k_spmm<<<NN, 128>>>(x, 0);
    k_spmm<<<NN, 128>>>(x, 1);

    // fully fused GEMM chain -> out (BM=64, 256 threads, 2 CTAs/SM — R11 proven)
    k_fused<<<MROWS/64, 256, SMEM_GEMM>>>(x, sage_b, attn_ln_g, attn_ln_b,
                                          lin_b, ln_g, ln_b, out);
}